// round 16
// baseline (speedup 1.0000x reference)
#include <cuda_runtime.h>
#include <cstdint>

// Model_PDE_2: N=131072, H=1024, D=2.  R16: f16x2 pipeline.
// - z in fp32 FFMA; pack f16x2; tanh.approx.f16x2 (2 tanh per MUFU op)
// - u = (1-t)(1+t), t3 = t*u in packed f16x2 (Sterbenz: 1-t exact)
// - mma.sync.m16n8k16.f16 (K=16 -> half the mma count of tf32 K=8)
// - H-split halves + 2 point tiles/warp + fused fold epilogue (as R15)
//   col0: out = sum t*w ; col1: g0 = sum u*wa ; col2: g1 = sum u*wb
//   col3: dx = sum t3*wbb (wbb = -2*w*b^2)
//   pde = .5*x1^2 + g0 + .5*dx + .5*x1*g1 - (.25/3.6)*g1^2

#define HID 1024
#define HHALF 512
#define TPB 128
#define CTA_PTS 256
#define NBLK (HHALF / 16)  // 32 blocks of 16 h
#define PAIRS (HHALF / 2)  // 256 f16x2 pairs
#define WT_S 264           // pair-row stride (256 + 8 pad)
#define NMAX 131072
#define NPTILE (NMAX / CTA_PTS)  // 512
#define ONE2 0x3C003C00u

__device__ float2 g_pA[2 * NMAX];  // per-half partials {out, g0}
__device__ float2 g_pB[2 * NMAX];  // per-half partials {g1, dx}
__device__ int g_ticket[NPTILE];   // zero-init; reset each run

__device__ __forceinline__ uint32_t pack2(float lo, float hi) {
    uint32_t r;
    asm("cvt.rn.f16x2.f32 %0, %1, %2;" : "=r"(r) : "f"(hi), "f"(lo));
    return r;
}
__device__ __forceinline__ uint32_t tanh2(uint32_t z2) {
    uint32_t t;
    asm("tanh.approx.f16x2 %0, %1;" : "=r"(t) : "r"(z2));
    return t;
}
__device__ __forceinline__ uint32_t hmul2(uint32_t a, uint32_t b) {
    uint32_t d;
    asm("mul.rn.f16x2 %0, %1, %2;" : "=r"(d) : "r"(a), "r"(b));
    return d;
}
__device__ __forceinline__ uint32_t hsub2(uint32_t a, uint32_t b) {
    uint32_t d;
    asm("sub.rn.f16x2 %0, %1, %2;" : "=r"(d) : "r"(a), "r"(b));
    return d;
}
__device__ __forceinline__ uint32_t hadd2(uint32_t a, uint32_t b) {
    uint32_t d;
    asm("add.rn.f16x2 %0, %1, %2;" : "=r"(d) : "r"(a), "r"(b));
    return d;
}
__device__ __forceinline__ void mma_f16(float* d, uint32_t a0, uint32_t a1,
                                        uint32_t a2, uint32_t a3, uint32_t b0,
                                        uint32_t b1) {
    asm volatile(
        "mma.sync.aligned.m16n8k16.row.col.f32.f16.f16.f32 "
        "{%0,%1,%2,%3}, {%4,%5,%6,%7}, {%8,%9}, {%0,%1,%2,%3};"
        : "+f"(d[0]), "+f"(d[1]), "+f"(d[2]), "+f"(d[3])
        : "r"(a0), "r"(a1), "r"(a2), "r"(a3), "r"(b0), "r"(b1));
}

__global__ __launch_bounds__(TPB, 7) void pde_main(
    const float* __restrict__ x, const float* __restrict__ W1,
    const float* __restrict__ b1, const float* __restrict__ w2,
    const float* __restrict__ b2, float* __restrict__ out, int N) {
    __shared__ float4 s_abc[HHALF];       // 8 KB {a,b,c,0} fp32
    __shared__ uint32_t s_w2[PAIRS];      // 1 KB  w pairs f16x2
    __shared__ uint32_t s_wt[3 * WT_S];   // 3.1 KB rows {wa, wb, wbb} pairs
    __shared__ int s_ticket;

    int tid = threadIdx.x;
    int half = blockIdx.x & 1;
    int ptile = blockIdx.x >> 1;
    int hoff = half * HHALF;

    for (int p = tid; p < PAIRS; p += TPB) {
        int h = hoff + 2 * p;
        float2 ab0 = reinterpret_cast<const float2*>(W1)[h];
        float2 ab1 = reinterpret_cast<const float2*>(W1)[h + 1];
        float c0 = b1[h], c1 = b1[h + 1];
        float w0 = w2[h], w1 = w2[h + 1];
        s_abc[2 * p] = make_float4(ab0.x, ab0.y, c0, 0.f);
        s_abc[2 * p + 1] = make_float4(ab1.x, ab1.y, c1, 0.f);
        s_w2[p] = pack2(w0, w1);
        s_wt[0 * WT_S + p] = pack2(w0 * ab0.x, w1 * ab1.x);  // wa
        s_wt[1 * WT_S + p] = pack2(w0 * ab0.y, w1 * ab1.y);  // wb
        s_wt[2 * WT_S + p] = pack2(-2.0f * w0 * ab0.y * ab0.y,
                                   -2.0f * w1 * ab1.y * ab1.y);  // wbb
    }
    __syncthreads();

    int lane = tid & 31;
    int wid = tid >> 5;
    int g = lane >> 2;   // output column n / row base
    int tig = lane & 3;  // k sub-col
    int n = g;
    int row = (n == 2) ? 1 : (n == 3) ? 2 : 0;
    const uint32_t* wtp = s_wt + row * WT_S;
    bool gate0 = (n == 0);
    bool gate1 = (n == 1 || n == 2);
    bool gate2 = (n == 3);

    int base_pt = ptile * CTA_PTS + wid * 64;

    float2 mxA = reinterpret_cast<const float2*>(x)[base_pt + lane];
    float2 mxB = reinterpret_cast<const float2*>(x)[base_pt + 32 + lane];
    float x0A[4], x1A[4], x0B[4], x1B[4];
#pragma unroll
    for (int i = 0; i < 4; i++) {
        x0A[i] = __shfl_sync(0xffffffffu, mxA.x, g + 8 * i);
        x1A[i] = __shfl_sync(0xffffffffu, mxA.y, g + 8 * i);
        x0B[i] = __shfl_sync(0xffffffffu, mxB.x, g + 8 * i);
        x1B[i] = __shfl_sync(0xffffffffu, mxB.y, g + 8 * i);
    }

    float accAlo[4] = {0.f, 0.f, 0.f, 0.f};
    float accAhi[4] = {0.f, 0.f, 0.f, 0.f};
    float accBlo[4] = {0.f, 0.f, 0.f, 0.f};
    float accBhi[4] = {0.f, 0.f, 0.f, 0.f};

// Per tile: 3 stages of m16n8k16 mma; A-frag: a0=row g pair(2tig,2tig+1),
// a1=row g+8 same, a2=row g pair(2tig+8,+9), a3=row g+8 hi pair.
#define ZV(x0v, x1v, r, e) \
    __fmaf_rn(x1v[r], e.y, __fmaf_rn(x0v[r], e.x, e.z))
#define TILE(x0v, x1v, accLo, accHi)                                        \
    do {                                                                    \
        uint32_t t0 = tanh2(pack2(ZV(x0v, x1v, 0, e00), ZV(x0v, x1v, 0, e01))); \
        uint32_t t1 = tanh2(pack2(ZV(x0v, x1v, 1, e00), ZV(x0v, x1v, 1, e01))); \
        uint32_t t2 = tanh2(pack2(ZV(x0v, x1v, 0, e10), ZV(x0v, x1v, 0, e11))); \
        uint32_t t3 = tanh2(pack2(ZV(x0v, x1v, 1, e10), ZV(x0v, x1v, 1, e11))); \
        uint32_t t4 = tanh2(pack2(ZV(x0v, x1v, 2, e00), ZV(x0v, x1v, 2, e01))); \
        uint32_t t5 = tanh2(pack2(ZV(x0v, x1v, 3, e00), ZV(x0v, x1v, 3, e01))); \
        uint32_t t6 = tanh2(pack2(ZV(x0v, x1v, 2, e10), ZV(x0v, x1v, 2, e11))); \
        uint32_t t7 = tanh2(pack2(ZV(x0v, x1v, 3, e10), ZV(x0v, x1v, 3, e11))); \
        mma_f16(accLo, t0, t1, t2, t3, b00, b01);                           \
        mma_f16(accHi, t4, t5, t6, t7, b00, b01);                           \
        uint32_t u0 = hmul2(hsub2(ONE2, t0), hadd2(ONE2, t0));              \
        uint32_t u1 = hmul2(hsub2(ONE2, t1), hadd2(ONE2, t1));              \
        uint32_t u2 = hmul2(hsub2(ONE2, t2), hadd2(ONE2, t2));              \
        uint32_t u3 = hmul2(hsub2(ONE2, t3), hadd2(ONE2, t3));              \
        uint32_t u4 = hmul2(hsub2(ONE2, t4), hadd2(ONE2, t4));              \
        uint32_t u5 = hmul2(hsub2(ONE2, t5), hadd2(ONE2, t5));              \
        uint32_t u6 = hmul2(hsub2(ONE2, t6), hadd2(ONE2, t6));              \
        uint32_t u7 = hmul2(hsub2(ONE2, t7), hadd2(ONE2, t7));              \
        mma_f16(accLo, u0, u1, u2, u3, b10, b11);                           \
        mma_f16(accHi, u4, u5, u6, u7, b10, b11);                           \
        t0 = hmul2(t0, u0);                                                 \
        t1 = hmul2(t1, u1);                                                 \
        t2 = hmul2(t2, u2);                                                 \
        t3 = hmul2(t3, u3);                                                 \
        t4 = hmul2(t4, u4);                                                 \
        t5 = hmul2(t5, u5);                                                 \
        t6 = hmul2(t6, u6);                                                 \
        t7 = hmul2(t7, u7);                                                 \
        mma_f16(accLo, t0, t1, t2, t3, b20, b21);                           \
        mma_f16(accHi, t4, t5, t6, t7, b20, b21);                           \
    } while (0)

    for (int b = 0; b < NBLK; b++) {
        int hp0 = b * 16 + 2 * tig;
        int hp1 = hp0 + 8;
        float4 e00 = s_abc[hp0];
        float4 e01 = s_abc[hp0 + 1];
        float4 e10 = s_abc[hp1];
        float4 e11 = s_abc[hp1 + 1];
        int pidx = b * 8 + tig;
        uint32_t wp0 = s_w2[pidx], wp1 = s_w2[pidx + 4];
        uint32_t sp0 = wtp[pidx], sp1 = wtp[pidx + 4];
        uint32_t b00 = gate0 ? wp0 : 0u, b01 = gate0 ? wp1 : 0u;
        uint32_t b10 = gate1 ? sp0 : 0u, b11 = gate1 ? sp1 : 0u;
        uint32_t b20 = gate2 ? sp0 : 0u, b21 = gate2 ? sp1 : 0u;

        TILE(x0A, x1A, accAlo, accAhi);
        TILE(x0B, x1B, accBlo, accBhi);
    }

    // Partial store: tig0 holds cols {0,1} = {out,g0}; tig1 holds {2,3} = {g1,dx}.
    int sA = half * NMAX + base_pt + g;
    int sB = sA + 32;
    if (tig == 0) {
        g_pA[sA + 0] = make_float2(accAlo[0], accAlo[1]);
        g_pA[sA + 8] = make_float2(accAlo[2], accAlo[3]);
        g_pA[sA + 16] = make_float2(accAhi[0], accAhi[1]);
        g_pA[sA + 24] = make_float2(accAhi[2], accAhi[3]);
        g_pA[sB + 0] = make_float2(accBlo[0], accBlo[1]);
        g_pA[sB + 8] = make_float2(accBlo[2], accBlo[3]);
        g_pA[sB + 16] = make_float2(accBhi[0], accBhi[1]);
        g_pA[sB + 24] = make_float2(accBhi[2], accBhi[3]);
    } else if (tig == 1) {
        g_pB[sA + 0] = make_float2(accAlo[0], accAlo[1]);
        g_pB[sA + 8] = make_float2(accAlo[2], accAlo[3]);
        g_pB[sA + 16] = make_float2(accAhi[0], accAhi[1]);
        g_pB[sA + 24] = make_float2(accAhi[2], accAhi[3]);
        g_pB[sB + 0] = make_float2(accBlo[0], accBlo[1]);
        g_pB[sB + 8] = make_float2(accBlo[2], accBlo[3]);
        g_pB[sB + 16] = make_float2(accBhi[0], accBhi[1]);
        g_pB[sB + 24] = make_float2(accBhi[2], accBhi[3]);
    }

    // ---- fused fold: second-arriving CTA of this ptile finalizes ----
    __threadfence();
    __syncthreads();
    if (tid == 0) s_ticket = atomicAdd(&g_ticket[ptile], 1);
    __syncthreads();
    if (s_ticket == 1) {
        float bz = b2[0];
#pragma unroll
        for (int i = 0; i < CTA_PTS / TPB; i++) {
            int p = ptile * CTA_PTS + i * TPB + tid;
            float2 a0 = g_pA[p];
            float2 a1 = g_pA[NMAX + p];
            float2 bb0 = g_pB[p];
            float2 bb1 = g_pB[NMAX + p];
            float x1v = reinterpret_cast<const float2*>(x)[p].y;

            float ov = a0.x + a1.x;
            float g0v = a0.y + a1.y;
            float g1v = bb0.x + bb1.x;
            float dxv = bb0.y + bb1.y;

            float pde = __fmaf_rn(0.5f * x1v, x1v, g0v);
            pde = __fmaf_rn(0.5f, dxv, pde);
            pde = __fmaf_rn(0.5f * x1v, g1v, pde);
            pde = __fmaf_rn(-0.069444444444444444f * g1v, g1v, pde);

            out[p] = ov + bz;
            out[N + p] = pde;
        }
        if (tid == 0) g_ticket[ptile] = 0;  // reset for next graph replay
    }
}

extern "C" void kernel_launch(void* const* d_in, const int* in_sizes, int n_in,
                              void* d_out, int out_size) {
    const float* x = (const float*)d_in[0];
    const float* W1 = (const float*)d_in[1];
    const float* b1 = (const float*)d_in[2];
    const float* w2 = (const float*)d_in[3];
    const float* b2 = (const float*)d_in[4];
    int N = in_sizes[0] / 2;

    pde_main<<<(N / CTA_PTS) * 2, TPB>>>(x, W1, b1, w2, b2, (float*)d_out, N);
}

// round 17
// speedup vs baseline: 1.2524x; 1.2524x over previous
#include <cuda_runtime.h>
#include <cstdint>

// Model_PDE_2: N=131072, H=1024, D=2.  R17: full-f16x2 inner pipeline.
// - weights pre-packed f16x2 pairs in smem ({a,b,c,w} = one uint4, LDS.128)
// - z = hfma2(x1,b,hfma2(x0,a,c)) in packed f16 ; tanh.approx.f16x2
// - u = fma2(-t,t,1) (XOR-neg on alu pipe), t3 = t*u ; zero CVT in loop
// - mma.sync.m16n8k16.f16 (half the mma count of tf32)
// - H-split halves + 2 point tiles/warp + fused fold epilogue (as R15)
//   col0: out = sum t*w ; col1: g0 = sum u*wa ; col2: g1 = sum u*wb
//   col3: dx = sum t3*wbb (wbb = -2*w*b^2)
//   pde = .5*x1^2 + g0 + .5*dx + .5*x1*g1 - (.25/3.6)*g1^2

#define HID 1024
#define HHALF 512
#define TPB 128
#define CTA_PTS 256
#define NBLK (HHALF / 16)  // 32 blocks of 16 h
#define PAIRS (HHALF / 2)  // 256 f16x2 pairs
#define WT_S 264           // pair-row stride (256 + 8 pad)
#define NMAX 131072
#define NPTILE (NMAX / CTA_PTS)  // 512
#define ONE2 0x3C003C00u
#define NEG2 0x80008000u

__device__ float2 g_pA[2 * NMAX];  // per-half partials {out, g0}
__device__ float2 g_pB[2 * NMAX];  // per-half partials {g1, dx}
__device__ int g_ticket[NPTILE];   // zero-init; reset each run

__device__ __forceinline__ uint32_t pack2(float lo, float hi) {
    uint32_t r;
    asm("cvt.rn.f16x2.f32 %0, %1, %2;" : "=r"(r) : "f"(hi), "f"(lo));
    return r;
}
__device__ __forceinline__ uint32_t tanh2(uint32_t z2) {
    uint32_t t;
    asm("tanh.approx.f16x2 %0, %1;" : "=r"(t) : "r"(z2));
    return t;
}
__device__ __forceinline__ uint32_t hfma2(uint32_t a, uint32_t b, uint32_t c) {
    uint32_t d;
    asm("fma.rn.f16x2 %0, %1, %2, %3;" : "=r"(d) : "r"(a), "r"(b), "r"(c));
    return d;
}
__device__ __forceinline__ uint32_t hmul2(uint32_t a, uint32_t b) {
    uint32_t d;
    asm("mul.rn.f16x2 %0, %1, %2;" : "=r"(d) : "r"(a), "r"(b));
    return d;
}
__device__ __forceinline__ void mma_f16(float* d, uint32_t a0, uint32_t a1,
                                        uint32_t a2, uint32_t a3, uint32_t b0,
                                        uint32_t b1) {
    asm volatile(
        "mma.sync.aligned.m16n8k16.row.col.f32.f16.f16.f32 "
        "{%0,%1,%2,%3}, {%4,%5,%6,%7}, {%8,%9}, {%0,%1,%2,%3};"
        : "+f"(d[0]), "+f"(d[1]), "+f"(d[2]), "+f"(d[3])
        : "r"(a0), "r"(a1), "r"(a2), "r"(a3), "r"(b0), "r"(b1));
}

__global__ __launch_bounds__(TPB, 7) void pde_main(
    const float* __restrict__ x, const float* __restrict__ W1,
    const float* __restrict__ b1, const float* __restrict__ w2,
    const float* __restrict__ b2, float* __restrict__ out, int N) {
    __shared__ uint4 s_abcw[PAIRS];      // 4 KB {a2,b2,c2,w2} f16x2 pairs
    __shared__ uint32_t s_wt[3 * WT_S];  // 3.1 KB rows {wa, wb, wbb} pairs
    __shared__ int s_ticket;

    int tid = threadIdx.x;
    int half = blockIdx.x & 1;
    int ptile = blockIdx.x >> 1;
    int hoff = half * HHALF;

    for (int p = tid; p < PAIRS; p += TPB) {
        int h = hoff + 2 * p;
        float2 ab0 = reinterpret_cast<const float2*>(W1)[h];
        float2 ab1 = reinterpret_cast<const float2*>(W1)[h + 1];
        float c0 = b1[h], c1 = b1[h + 1];
        float w0 = w2[h], w1 = w2[h + 1];
        s_abcw[p] = make_uint4(pack2(ab0.x, ab1.x), pack2(ab0.y, ab1.y),
                               pack2(c0, c1), pack2(w0, w1));
        s_wt[0 * WT_S + p] = pack2(w0 * ab0.x, w1 * ab1.x);  // wa
        s_wt[1 * WT_S + p] = pack2(w0 * ab0.y, w1 * ab1.y);  // wb
        s_wt[2 * WT_S + p] = pack2(-2.0f * w0 * ab0.y * ab0.y,
                                   -2.0f * w1 * ab1.y * ab1.y);  // wbb
    }
    __syncthreads();

    int lane = tid & 31;
    int wid = tid >> 5;
    int g = lane >> 2;   // output column n / row base
    int tig = lane & 3;  // k sub-col
    int n = g;
    int row = (n == 2) ? 1 : (n == 3) ? 2 : 0;
    const uint32_t* wtp = s_wt + row * WT_S;
    bool gate0 = (n == 0);
    bool gate1 = (n == 1 || n == 2);
    bool gate2 = (n == 3);

    int base_pt = ptile * CTA_PTS + wid * 64;

    float2 mxA = reinterpret_cast<const float2*>(x)[base_pt + lane];
    float2 mxB = reinterpret_cast<const float2*>(x)[base_pt + 32 + lane];
    // Duplicated f16x2 packs of x per fragment row (converted once).
    uint32_t x0A[4], x1A[4], x0B[4], x1B[4];
#pragma unroll
    for (int i = 0; i < 4; i++) {
        float v;
        v = __shfl_sync(0xffffffffu, mxA.x, g + 8 * i);
        x0A[i] = pack2(v, v);
        v = __shfl_sync(0xffffffffu, mxA.y, g + 8 * i);
        x1A[i] = pack2(v, v);
        v = __shfl_sync(0xffffffffu, mxB.x, g + 8 * i);
        x0B[i] = pack2(v, v);
        v = __shfl_sync(0xffffffffu, mxB.y, g + 8 * i);
        x1B[i] = pack2(v, v);
    }

    float accAlo[4] = {0.f, 0.f, 0.f, 0.f};
    float accAhi[4] = {0.f, 0.f, 0.f, 0.f};
    float accBlo[4] = {0.f, 0.f, 0.f, 0.f};
    float accBhi[4] = {0.f, 0.f, 0.f, 0.f};

// z for (row-pack xd0/xd1, h-pair a/b/c): 2 HFMA2 -> tanh2
#define ZT(x0d, x1d, ap, bp, cp) tanh2(hfma2(x1d, bp, hfma2(x0d, ap, cp)))
#define TILE(x0v, x1v, accLo, accHi)                                     \
    do {                                                                 \
        uint32_t t0 = ZT(x0v[0], x1v[0], a0p, b0p, c0p);                 \
        uint32_t t1 = ZT(x0v[1], x1v[1], a0p, b0p, c0p);                 \
        uint32_t t2 = ZT(x0v[0], x1v[0], a1p, b1p, c1p);                 \
        uint32_t t3 = ZT(x0v[1], x1v[1], a1p, b1p, c1p);                 \
        uint32_t t4 = ZT(x0v[2], x1v[2], a0p, b0p, c0p);                 \
        uint32_t t5 = ZT(x0v[3], x1v[3], a0p, b0p, c0p);                 \
        uint32_t t6 = ZT(x0v[2], x1v[2], a1p, b1p, c1p);                 \
        uint32_t t7 = ZT(x0v[3], x1v[3], a1p, b1p, c1p);                 \
        mma_f16(accLo, t0, t1, t2, t3, b00, b01);                        \
        mma_f16(accHi, t4, t5, t6, t7, b00, b01);                        \
        uint32_t u0 = hfma2(t0 ^ NEG2, t0, ONE2);                        \
        uint32_t u1 = hfma2(t1 ^ NEG2, t1, ONE2);                        \
        uint32_t u2 = hfma2(t2 ^ NEG2, t2, ONE2);                        \
        uint32_t u3 = hfma2(t3 ^ NEG2, t3, ONE2);                        \
        uint32_t u4 = hfma2(t4 ^ NEG2, t4, ONE2);                        \
        uint32_t u5 = hfma2(t5 ^ NEG2, t5, ONE2);                        \
        uint32_t u6 = hfma2(t6 ^ NEG2, t6, ONE2);                        \
        uint32_t u7 = hfma2(t7 ^ NEG2, t7, ONE2);                        \
        mma_f16(accLo, u0, u1, u2, u3, b10, b11);                        \
        mma_f16(accHi, u4, u5, u6, u7, b10, b11);                        \
        t0 = hmul2(t0, u0);                                              \
        t1 = hmul2(t1, u1);                                              \
        t2 = hmul2(t2, u2);                                              \
        t3 = hmul2(t3, u3);                                              \
        t4 = hmul2(t4, u4);                                              \
        t5 = hmul2(t5, u5);                                              \
        t6 = hmul2(t6, u6);                                              \
        t7 = hmul2(t7, u7);                                              \
        mma_f16(accLo, t0, t1, t2, t3, b20, b21);                        \
        mma_f16(accHi, t4, t5, t6, t7, b20, b21);                        \
    } while (0)

    for (int b = 0; b < NBLK; b++) {
        int pidx = b * 8 + tig;
        uint4 q0 = s_abcw[pidx];      // h-pair (2tig, 2tig+1)
        uint4 q1 = s_abcw[pidx + 4];  // h-pair (+8)
        uint32_t a0p = q0.x, b0p = q0.y, c0p = q0.z;
        uint32_t a1p = q1.x, b1p = q1.y, c1p = q1.z;
        uint32_t sp0 = wtp[pidx], sp1 = wtp[pidx + 4];
        uint32_t b00 = gate0 ? q0.w : 0u, b01 = gate0 ? q1.w : 0u;
        uint32_t b10 = gate1 ? sp0 : 0u, b11 = gate1 ? sp1 : 0u;
        uint32_t b20 = gate2 ? sp0 : 0u, b21 = gate2 ? sp1 : 0u;

        TILE(x0A, x1A, accAlo, accAhi);
        TILE(x0B, x1B, accBlo, accBhi);
    }

    // Partial store: tig0 holds cols {0,1} = {out,g0}; tig1 holds {2,3} = {g1,dx}.
    int sA = half * NMAX + base_pt + g;
    int sB = sA + 32;
    if (tig == 0) {
        g_pA[sA + 0] = make_float2(accAlo[0], accAlo[1]);
        g_pA[sA + 8] = make_float2(accAlo[2], accAlo[3]);
        g_pA[sA + 16] = make_float2(accAhi[0], accAhi[1]);
        g_pA[sA + 24] = make_float2(accAhi[2], accAhi[3]);
        g_pA[sB + 0] = make_float2(accBlo[0], accBlo[1]);
        g_pA[sB + 8] = make_float2(accBlo[2], accBlo[3]);
        g_pA[sB + 16] = make_float2(accBhi[0], accBhi[1]);
        g_pA[sB + 24] = make_float2(accBhi[2], accBhi[3]);
    } else if (tig == 1) {
        g_pB[sA + 0] = make_float2(accAlo[0], accAlo[1]);
        g_pB[sA + 8] = make_float2(accAlo[2], accAlo[3]);
        g_pB[sA + 16] = make_float2(accAhi[0], accAhi[1]);
        g_pB[sA + 24] = make_float2(accAhi[2], accAhi[3]);
        g_pB[sB + 0] = make_float2(accBlo[0], accBlo[1]);
        g_pB[sB + 8] = make_float2(accBlo[2], accBlo[3]);
        g_pB[sB + 16] = make_float2(accBhi[0], accBhi[1]);
        g_pB[sB + 24] = make_float2(accBhi[2], accBhi[3]);
    }

    // ---- fused fold: second-arriving CTA of this ptile finalizes ----
    __threadfence();
    __syncthreads();
    if (tid == 0) s_ticket = atomicAdd(&g_ticket[ptile], 1);
    __syncthreads();
    if (s_ticket == 1) {
        float bz = b2[0];
#pragma unroll
        for (int i = 0; i < CTA_PTS / TPB; i++) {
            int p = ptile * CTA_PTS + i * TPB + tid;
            float2 a0 = g_pA[p];
            float2 a1 = g_pA[NMAX + p];
            float2 bb0 = g_pB[p];
            float2 bb1 = g_pB[NMAX + p];
            float x1v = reinterpret_cast<const float2*>(x)[p].y;

            float ov = a0.x + a1.x;
            float g0v = a0.y + a1.y;
            float g1v = bb0.x + bb1.x;
            float dxv = bb0.y + bb1.y;

            float pde = __fmaf_rn(0.5f * x1v, x1v, g0v);
            pde = __fmaf_rn(0.5f, dxv, pde);
            pde = __fmaf_rn(0.5f * x1v, g1v, pde);
            pde = __fmaf_rn(-0.069444444444444444f * g1v, g1v, pde);

            out[p] = ov + bz;
            out[N + p] = pde;
        }
        if (tid == 0) g_ticket[ptile] = 0;  // reset for next graph replay
    }
}

extern "C" void kernel_launch(void* const* d_in, const int* in_sizes, int n_in,
                              void* d_out, int out_size) {
    const float* x = (const float*)d_in[0];
    const float* W1 = (const float*)d_in[1];
    const float* b1 = (const float*)d_in[2];
    const float* w2 = (const float*)d_in[3];
    const float* b2 = (const float*)d_in[4];
    int N = in_sizes[0] / 2;

    pde_main<<<(N / CTA_PTS) * 2, TPB>>>(x, W1, b1, w2, b2, (float*)d_out, N);
}